// round 2
// baseline (speedup 1.0000x reference)
#include <cuda_runtime.h>
#include <math.h>

#define N_NODES 100000
#define N_EDGES 1250000
#define D 64
#define N_LAYERS 4
#define WPB 16           // warps (=nodes) per block in layer kernel
#define TPB (WPB * 32)

// ---------------- scratch (static device globals; no runtime alloc) --------
__device__ float g_buf0[N_NODES * D];
__device__ float g_buf1[N_NODES * D];
__device__ int   g_counts[N_NODES];
__device__ int   g_rowptr[N_NODES + 1];
__device__ int   g_cursor[N_NODES];
__device__ int   g_csr[N_EDGES];
__device__ int   g_is64;

// ---------------- dtype detection ------------------------------------------
// If edge_index is really int64, every sampled int64 value lies in [0, N_NODES).
// If it's int32, the int64 view fuses two random node ids -> almost surely huge.
__global__ void detect_kernel(const void* __restrict__ edge_raw) {
    if (threadIdx.x == 0 && blockIdx.x == 0) {
        const long long* e64 = (const long long*)edge_raw;
        int ok64 = 1;
        for (int i = 0; i < 64; i++) {
            long long v = e64[i];
            if (v < 0 || v >= N_NODES) { ok64 = 0; break; }
        }
        g_is64 = ok64;
    }
}

__device__ __forceinline__ int load_edge(const void* edge_raw, long long idx, int is64) {
    if (is64) return (int)((const long long*)edge_raw)[idx];
    return ((const int*)edge_raw)[idx];
}

// ---------------- CSR build -------------------------------------------------
__global__ void zero_counts_kernel() {
    int i = blockIdx.x * blockDim.x + threadIdx.x;
    if (i < N_NODES) g_counts[i] = 0;
}

__global__ void histogram_kernel(const void* __restrict__ edge_raw) {
    int e = blockIdx.x * blockDim.x + threadIdx.x;
    if (e >= N_EDGES) return;
    int is64 = g_is64;
    int dst = load_edge(edge_raw, (long long)N_EDGES + e, is64);
    if (dst < 0 || dst >= N_NODES) return;   // defensive: never fault
    atomicAdd(&g_counts[dst], 1);
}

// Single-block exclusive scan over g_counts -> g_rowptr (+ copy to g_cursor)
__global__ __launch_bounds__(1024) void scan_kernel() {
    __shared__ int warpsums[32];
    __shared__ int s_carry;
    int tid = threadIdx.x;
    int lane = tid & 31, w = tid >> 5;
    if (tid == 0) s_carry = 0;
    __syncthreads();

    for (int base = 0; base < N_NODES; base += 1024) {
        int i = base + tid;
        int v = (i < N_NODES) ? g_counts[i] : 0;

        // warp inclusive scan
        int x = v;
        #pragma unroll
        for (int off = 1; off < 32; off <<= 1) {
            int y = __shfl_up_sync(0xffffffffu, x, off);
            if (lane >= off) x += y;
        }
        if (lane == 31) warpsums[w] = x;
        __syncthreads();
        if (w == 0) {
            int s = warpsums[lane];
            #pragma unroll
            for (int off = 1; off < 32; off <<= 1) {
                int y = __shfl_up_sync(0xffffffffu, s, off);
                if (lane >= off) s += y;
            }
            warpsums[lane] = s;
        }
        __syncthreads();
        int wprefix = (w > 0) ? warpsums[w - 1] : 0;
        int incl = x + wprefix;
        int excl = s_carry + incl - v;
        if (i < N_NODES) {
            g_rowptr[i] = excl;
            g_cursor[i] = excl;
        }
        __syncthreads();
        if (tid == 1023) s_carry += incl;   // incl of last thread == chunk total
        __syncthreads();
    }
    if (tid == 0) g_rowptr[N_NODES] = s_carry;
}

__global__ void scatter_kernel(const void* __restrict__ edge_raw) {
    int e = blockIdx.x * blockDim.x + threadIdx.x;
    if (e >= N_EDGES) return;
    int is64 = g_is64;
    int src = load_edge(edge_raw, e, is64);
    int dst = load_edge(edge_raw, (long long)N_EDGES + e, is64);
    if (src < 0 || src >= N_NODES || dst < 0 || dst >= N_NODES) return;
    int pos = atomicAdd(&g_cursor[dst], 1);
    if (pos >= 0 && pos < N_EDGES)
        g_csr[pos] = src;   // order within a segment irrelevant: max is commutative
}

// ---------------- fused layer: segment-max agg + 2 GEMMs + bias + relu ------
// One warp per node. Lane owns output dims (2*lane, 2*lane+1) as a float2.
__global__ __launch_bounds__(TPB) void layer_kernel(
    const float* __restrict__ x_ext, float* __restrict__ out_ext,
    const float* __restrict__ Wl, const float* __restrict__ bl,
    const float* __restrict__ Wr,
    int layer, int in_mode, int out_mode)
{
    const float* h_in  = (in_mode  == 0) ? x_ext  : ((in_mode  == 1) ? g_buf0 : g_buf1);
    float*       h_out = (out_mode == 0) ? out_ext : ((out_mode == 1) ? g_buf0 : g_buf1);

    __shared__ __align__(16) float sWl[D * D];
    __shared__ __align__(16) float sWr[D * D];
    __shared__ __align__(16) float sBl[D];
    __shared__ __align__(16) float sAgg[WPB][D];
    __shared__ __align__(16) float sH[WPB][D];

    int tid = threadIdx.x;
    const float* wl = Wl + layer * D * D;
    const float* wr = Wr + layer * D * D;
    // stage weights (float4 vectorized)
    for (int i = tid; i < D * D / 4; i += TPB) {
        ((float4*)sWl)[i] = ((const float4*)wl)[i];
        ((float4*)sWr)[i] = ((const float4*)wr)[i];
    }
    if (tid < D) sBl[tid] = bl[layer * D + tid];
    __syncthreads();

    int warp = tid >> 5, lane = tid & 31;
    int node = blockIdx.x * WPB + warp;
    if (node >= N_NODES) return;

    const float2* h2 = (const float2*)h_in;

    // ---- segment max aggregation ----
    int start = g_rowptr[node];
    int end   = g_rowptr[node + 1];
    float2 m = make_float2(-INFINITY, -INFINITY);

    int j = start;
    for (; j + 32 <= end; j += 32) {
        int s = g_csr[j + lane];
        #pragma unroll 8
        for (int t = 0; t < 32; t++) {
            int sv = __shfl_sync(0xffffffffu, s, t);
            float2 v = h2[sv * 32 + lane];
            m.x = fmaxf(m.x, v.x);
            m.y = fmaxf(m.y, v.y);
        }
    }
    if (j < end) {
        int idx = j + lane;
        int s = (idx < end) ? g_csr[idx] : 0;
        int cnt = end - j;
        for (int t = 0; t < cnt; t++) {
            int sv = __shfl_sync(0xffffffffu, s, t);
            float2 v = h2[sv * 32 + lane];
            m.x = fmaxf(m.x, v.x);
            m.y = fmaxf(m.y, v.y);
        }
    }
    // empty segments -> 0 (PyG convention)
    m.x = (m.x == -INFINITY) ? 0.0f : m.x;
    m.y = (m.y == -INFINITY) ? 0.0f : m.y;

    // stage agg row + self row in smem
    ((float2*)sAgg[warp])[lane] = m;
    float2 hv = h2[node * 32 + lane];
    ((float2*)sH[warp])[lane] = hv;
    __syncwarp();

    // ---- fused GEMMs: out = relu(agg@Wl + bl + h@Wr) ----
    float2 acc = make_float2(sBl[2 * lane], sBl[2 * lane + 1]);
    const float2* wl2 = (const float2*)sWl;
    const float2* wr2 = (const float2*)sWr;
    #pragma unroll 16
    for (int k = 0; k < D; k++) {
        float a  = sAgg[warp][k];
        float hh = sH[warp][k];
        float2 wlv = wl2[k * 32 + lane];
        float2 wrv = wr2[k * 32 + lane];
        acc.x += a * wlv.x + hh * wrv.x;
        acc.y += a * wlv.y + hh * wrv.y;
    }
    acc.x = fmaxf(acc.x, 0.0f);
    acc.y = fmaxf(acc.y, 0.0f);
    ((float2*)h_out)[node * 32 + lane] = acc;
}

// ---------------- launch -----------------------------------------------------
extern "C" void kernel_launch(void* const* d_in, const int* in_sizes, int n_in,
                              void* d_out, int out_size) {
    // Identify inputs by element count (robust to metadata ordering):
    //   x: N_NODES*D = 6.4M, edge: 2*N_EDGES = 2.5M,
    //   Wl/Wr: N_LAYERS*D*D = 16384 (Wl first), bl: N_LAYERS*D = 256.
    const float* x  = nullptr;
    const void*  edge = nullptr;
    const float* Wl = nullptr;
    const float* Wr = nullptr;
    const float* bl = nullptr;
    for (int i = 0; i < n_in; i++) {
        int sz = in_sizes[i];
        if (sz == N_NODES * D)            x    = (const float*)d_in[i];
        else if (sz == 2 * N_EDGES)       edge = d_in[i];
        else if (sz == N_LAYERS * D * D) { if (!Wl) Wl = (const float*)d_in[i];
                                           else     Wr = (const float*)d_in[i]; }
        else if (sz == N_LAYERS * D)      bl   = (const float*)d_in[i];
    }
    float* out = (float*)d_out;

    detect_kernel<<<1, 32>>>(edge);
    zero_counts_kernel<<<(N_NODES + 255) / 256, 256>>>();
    histogram_kernel<<<(N_EDGES + 255) / 256, 256>>>(edge);
    scan_kernel<<<1, 1024>>>();
    scatter_kernel<<<(N_EDGES + 255) / 256, 256>>>(edge);

    int blocks = (N_NODES + WPB - 1) / WPB;
    // ping-pong: x -> buf0 -> buf1 -> buf0 -> out
    layer_kernel<<<blocks, TPB>>>(x, out, Wl, bl, Wr, 0, 0, 1);
    layer_kernel<<<blocks, TPB>>>(x, out, Wl, bl, Wr, 1, 1, 2);
    layer_kernel<<<blocks, TPB>>>(x, out, Wl, bl, Wr, 2, 2, 1);
    layer_kernel<<<blocks, TPB>>>(x, out, Wl, bl, Wr, 3, 1, 0);
}

// round 3
// speedup vs baseline: 1.1320x; 1.1320x over previous
#include <cuda_runtime.h>
#include <math.h>

#define N_NODES 100000
#define N_EDGES 1250000
#define D 64
#define N_LAYERS 4

// ---- layer kernel config ----
#define TPB 256                       // 8 warps
#define N_TILES 4                     // 4 tiles of 32 nodes; 2 warps (dim-halves) per tile
#define NPB (N_TILES * 32)            // 128 nodes per block
#define PITCH 129                     // odd pitch -> conflict-free sA[lane][k] reads
#define SMEM_A_FLOATS (N_TILES * 32 * PITCH)
#define SMEM_W_FLOATS (2 * D * D)
#define SMEM_BYTES ((SMEM_A_FLOATS + SMEM_W_FLOATS + D) * 4)

// ---- scan config ----
#define SBLK 1024
#define NSB ((N_NODES + SBLK - 1) / SBLK)   // 98

// ---------------- scratch (static device globals) ---------------------------
__device__ float g_buf0[N_NODES * D];
__device__ float g_buf1[N_NODES * D];
__device__ int   g_counts[N_NODES];
__device__ int   g_rowptr[N_NODES + 1];
__device__ int   g_cursor[N_NODES];
__device__ int   g_csr[N_EDGES];
__device__ int   g_bsums[NSB];
__device__ int   g_total;
__device__ int   g_is64;

// ---------------- packed f32x2 helpers --------------------------------------
__device__ __forceinline__ unsigned long long pk(float x, float y) {
    unsigned long long r;
    asm("mov.b64 %0, {%1, %2};" : "=l"(r) : "f"(x), "f"(y));
    return r;
}
__device__ __forceinline__ void fma2(unsigned long long& d,
                                     unsigned long long a, unsigned long long b) {
    asm("fma.rn.f32x2 %0, %1, %2, %0;" : "+l"(d) : "l"(a), "l"(b));
}
__device__ __forceinline__ float2 upk(unsigned long long v) {
    float2 r;
    asm("mov.b64 {%0, %1}, %2;" : "=f"(r.x), "=f"(r.y) : "l"(v));
    return r;
}

// ---------------- dtype detection ------------------------------------------
__global__ void detect_kernel(const void* __restrict__ edge_raw) {
    if (threadIdx.x == 0 && blockIdx.x == 0) {
        const long long* e64 = (const long long*)edge_raw;
        int ok64 = 1;
        for (int i = 0; i < 64; i++) {
            long long v = e64[i];
            if (v < 0 || v >= N_NODES) { ok64 = 0; break; }
        }
        g_is64 = ok64;
    }
}

__device__ __forceinline__ int load_edge(const void* edge_raw, long long idx, int is64) {
    if (is64) return (int)((const long long*)edge_raw)[idx];
    return ((const int*)edge_raw)[idx];
}

// ---------------- CSR build -------------------------------------------------
__global__ void zero_counts_kernel() {
    int i = blockIdx.x * blockDim.x + threadIdx.x;
    if (i < N_NODES) g_counts[i] = 0;
}

__global__ void histogram_kernel(const void* __restrict__ edge_raw) {
    int e = blockIdx.x * blockDim.x + threadIdx.x;
    if (e >= N_EDGES) return;
    int dst = load_edge(edge_raw, (long long)N_EDGES + e, g_is64);
    if (dst < 0 || dst >= N_NODES) return;
    atomicAdd(&g_counts[dst], 1);
}

// phase 1: per-block exclusive scan + block totals
__global__ __launch_bounds__(SBLK) void scan1_kernel() {
    __shared__ int wsum[32];
    int tid = threadIdx.x, lane = tid & 31, w = tid >> 5;
    int i = blockIdx.x * SBLK + tid;
    int v = (i < N_NODES) ? g_counts[i] : 0;
    int x = v;
    #pragma unroll
    for (int off = 1; off < 32; off <<= 1) {
        int y = __shfl_up_sync(0xffffffffu, x, off);
        if (lane >= off) x += y;
    }
    if (lane == 31) wsum[w] = x;
    __syncthreads();
    if (w == 0) {
        int s = wsum[lane];
        #pragma unroll
        for (int off = 1; off < 32; off <<= 1) {
            int y = __shfl_up_sync(0xffffffffu, s, off);
            if (lane >= off) s += y;
        }
        wsum[lane] = s;
    }
    __syncthreads();
    int incl = x + ((w > 0) ? wsum[w - 1] : 0);
    if (i < N_NODES) g_rowptr[i] = incl - v;         // block-local exclusive
    if (tid == SBLK - 1) g_bsums[blockIdx.x] = incl; // block total
}

// phase 2: exclusive scan of NSB block totals (one 128-thread block)
__global__ void scan2_kernel() {
    __shared__ int wsum[4];
    int tid = threadIdx.x, lane = tid & 31, w = tid >> 5;
    int v = (tid < NSB) ? g_bsums[tid] : 0;
    int x = v;
    #pragma unroll
    for (int off = 1; off < 32; off <<= 1) {
        int y = __shfl_up_sync(0xffffffffu, x, off);
        if (lane >= off) x += y;
    }
    if (lane == 31) wsum[w] = x;
    __syncthreads();
    int wp = 0;
    for (int q = 0; q < w; q++) wp += wsum[q];
    int incl = x + wp;
    if (tid < NSB) g_bsums[tid] = incl - v;          // exclusive
    if (tid == 127) g_total = incl;                  // grand total (pads are 0)
}

// phase 3: add block offsets, init cursors, write rowptr[N]
__global__ __launch_bounds__(SBLK) void scan3_kernel() {
    int i = blockIdx.x * SBLK + threadIdx.x;
    if (i < N_NODES) {
        int r = g_rowptr[i] + g_bsums[blockIdx.x];
        g_rowptr[i] = r;
        g_cursor[i] = r;
    }
    if (blockIdx.x == 0 && threadIdx.x == 0) g_rowptr[N_NODES] = g_total;
}

__global__ void scatter_kernel(const void* __restrict__ edge_raw) {
    int e = blockIdx.x * blockDim.x + threadIdx.x;
    if (e >= N_EDGES) return;
    int is64 = g_is64;
    int src = load_edge(edge_raw, e, is64);
    int dst = load_edge(edge_raw, (long long)N_EDGES + e, is64);
    if (src < 0 || src >= N_NODES || dst < 0 || dst >= N_NODES) return;
    int pos = atomicAdd(&g_cursor[dst], 1);
    if (pos >= 0 && pos < N_EDGES) g_csr[pos] = src;
}

// ---------------- fused layer -----------------------------------------------
// Block = 128 nodes (4 tiles x 32). Gather: each warp max-pools 16 nodes into
// sA[node][0:64]=agg, [64:128]=self (pitch 129). GEMM: warp (tile, half): lane
// = node, computes 32 output dims with packed f32x2 FMA; weights LDS.128
// broadcast; A reads conflict-free.
__global__ __launch_bounds__(TPB) void layer_kernel(
    const float* __restrict__ x_ext, float* __restrict__ out_ext,
    const float* __restrict__ Wl, const float* __restrict__ bl,
    const float* __restrict__ Wr,
    int layer, int in_mode, int out_mode)
{
    extern __shared__ float smem[];
    float* sA = smem;
    float* sW = smem + SMEM_A_FLOATS;   // combined [128][64]: k<64 -> Wl, k>=64 -> Wr
    float* sB = sW + SMEM_W_FLOATS;

    const float* h_in  = (in_mode  == 0) ? x_ext  : ((in_mode  == 1) ? g_buf0 : g_buf1);
    float*       h_out = (out_mode == 0) ? out_ext : ((out_mode == 1) ? g_buf0 : g_buf1);

    int tid = threadIdx.x;
    {
        const float4* wl4 = (const float4*)(Wl + layer * D * D);
        const float4* wr4 = (const float4*)(Wr + layer * D * D);
        float4* sW4 = (float4*)sW;
        #pragma unroll
        for (int i = tid; i < D * D / 4; i += TPB) sW4[i] = wl4[i];
        #pragma unroll
        for (int i = tid; i < D * D / 4; i += TPB) sW4[D * D / 4 + i] = wr4[i];
        if (tid < D) sB[tid] = bl[layer * D + tid];
    }

    int warp = tid >> 5, lane = tid & 31;
    int tile = warp >> 1, half = warp & 1;
    int blockBase = blockIdx.x * NPB;
    const float2* h2 = (const float2*)h_in;

    // ---- gather phase: this warp max-pools 16 nodes ----
    for (int i = 0; i < 16; i++) {
        int nl = tile * 32 + half * 16 + i;
        int node = blockBase + nl;
        if (node >= N_NODES) break;
        int start = g_rowptr[node];
        int end   = g_rowptr[node + 1];
        float mx = -INFINITY, my = -INFINITY;
        for (int j = start; j < end; j += 32) {
            int idx = j + lane;
            int s = (idx < end) ? g_csr[idx] : 0;
            int cnt = end - j;
            if (cnt >= 32) {
                #pragma unroll 8
                for (int t = 0; t < 32; t++) {
                    int sv = __shfl_sync(0xffffffffu, s, t);
                    float2 v = h2[sv * 32 + lane];
                    mx = fmaxf(mx, v.x); my = fmaxf(my, v.y);
                }
            } else {
                for (int t = 0; t < cnt; t++) {
                    int sv = __shfl_sync(0xffffffffu, s, t);
                    float2 v = h2[sv * 32 + lane];
                    mx = fmaxf(mx, v.x); my = fmaxf(my, v.y);
                }
            }
        }
        if (mx == -INFINITY) mx = 0.0f;   // empty segment -> 0 (PyG)
        if (my == -INFINITY) my = 0.0f;
        float2 hv = h2[node * 32 + lane];
        float* arow = sA + nl * PITCH;
        arow[2 * lane]          = mx;
        arow[2 * lane + 1]      = my;
        arow[64 + 2 * lane]     = hv.x;
        arow[64 + 2 * lane + 1] = hv.y;
    }
    __syncthreads();

    // ---- GEMM phase: out = relu([agg|h] @ [Wl;Wr] + bl) ----
    int nl = tile * 32 + lane;           // lane = node within tile
    int node = blockBase + nl;
    const float* arow = sA + nl * PITCH;
    const float* wbase = sW + half * 32;

    unsigned long long acc[16];
    {
        const float* bb = sB + half * 32;
        #pragma unroll
        for (int j = 0; j < 16; j++) acc[j] = pk(bb[2 * j], bb[2 * j + 1]);
    }
    #pragma unroll 4
    for (int k = 0; k < 2 * D; k++) {
        float a = arow[k];                         // conflict-free (pitch 129)
        unsigned long long aa = pk(a, a);
        const ulonglong2* w2 = (const ulonglong2*)(wbase + k * D);
        #pragma unroll
        for (int j = 0; j < 8; j++) {
            ulonglong2 w = w2[j];                  // LDS.128 broadcast
            fma2(acc[2 * j],     aa, w.x);
            fma2(acc[2 * j + 1], aa, w.y);
        }
    }
    if (node < N_NODES) {
        float4* orow = (float4*)(h_out + node * D + half * 32);
        #pragma unroll
        for (int j = 0; j < 8; j++) {
            float2 p0 = upk(acc[2 * j]);
            float2 p1 = upk(acc[2 * j + 1]);
            float4 o;
            o.x = fmaxf(p0.x, 0.0f); o.y = fmaxf(p0.y, 0.0f);
            o.z = fmaxf(p1.x, 0.0f); o.w = fmaxf(p1.y, 0.0f);
            orow[j] = o;
        }
    }
}

// ---------------- launch -----------------------------------------------------
extern "C" void kernel_launch(void* const* d_in, const int* in_sizes, int n_in,
                              void* d_out, int out_size) {
    const float* x  = nullptr;
    const void*  edge = nullptr;
    const float* Wl = nullptr;
    const float* Wr = nullptr;
    const float* bl = nullptr;
    for (int i = 0; i < n_in; i++) {
        int sz = in_sizes[i];
        if (sz == N_NODES * D)            x    = (const float*)d_in[i];
        else if (sz == 2 * N_EDGES)       edge = d_in[i];
        else if (sz == N_LAYERS * D * D) { if (!Wl) Wl = (const float*)d_in[i];
                                           else     Wr = (const float*)d_in[i]; }
        else if (sz == N_LAYERS * D)      bl   = (const float*)d_in[i];
    }
    float* out = (float*)d_out;

    static int smem_set = 0;
    if (!smem_set) {
        cudaFuncSetAttribute(layer_kernel,
                             cudaFuncAttributeMaxDynamicSharedMemorySize, SMEM_BYTES);
        smem_set = 1;
    }

    detect_kernel<<<1, 32>>>(edge);
    zero_counts_kernel<<<(N_NODES + 255) / 256, 256>>>();
    histogram_kernel<<<(N_EDGES + 255) / 256, 256>>>(edge);
    scan1_kernel<<<NSB, SBLK>>>();
    scan2_kernel<<<1, 128>>>();
    scan3_kernel<<<NSB, SBLK>>>();
    scatter_kernel<<<(N_EDGES + 255) / 256, 256>>>(edge);

    int blocks = (N_NODES + NPB - 1) / NPB;
    layer_kernel<<<blocks, TPB, SMEM_BYTES>>>(x, out, Wl, bl, Wr, 0, 0, 1);
    layer_kernel<<<blocks, TPB, SMEM_BYTES>>>(x, out, Wl, bl, Wr, 1, 1, 2);
    layer_kernel<<<blocks, TPB, SMEM_BYTES>>>(x, out, Wl, bl, Wr, 2, 2, 1);
    layer_kernel<<<blocks, TPB, SMEM_BYTES>>>(x, out, Wl, bl, Wr, 3, 1, 0);
}

// round 4
// speedup vs baseline: 1.3471x; 1.1900x over previous
#include <cuda_runtime.h>
#include <math.h>

#define N_NODES 100000
#define N_EDGES 1250000
#define D 64
#define N_LAYERS 4

// ---- layer kernel config ----
#define TPB 256                       // 8 warps
#define N_TILES 4                     // 4 tiles of 32 nodes; 2 warps (dim-halves) per tile
#define NPB (N_TILES * 32)            // 128 nodes per block
#define PITCH 129                     // odd pitch -> conflict-free sA[lane][k] reads
#define SMEM_A_FLOATS (N_TILES * 32 * PITCH)
#define SMEM_W_FLOATS (2 * D * D)
#define SMEM_BYTES ((SMEM_A_FLOATS + SMEM_W_FLOATS + D) * 4)

// ---- scan config ----
#define SBLK 1024
#define NSB ((N_NODES + SBLK - 1) / SBLK)   // 98

// ---------------- scratch (static device globals) ---------------------------
__device__ float g_buf0[N_NODES * D];
__device__ float g_buf1[N_NODES * D];
__device__ int   g_counts[N_NODES];
__device__ int   g_rowptr[N_NODES + 1];
__device__ int   g_cursor[N_NODES];
__device__ int   g_csr[N_EDGES];
__device__ int   g_bsums[NSB];
__device__ int   g_total;
__device__ int   g_is64;

// ---------------- packed f32x2 helpers --------------------------------------
__device__ __forceinline__ unsigned long long pk(float x, float y) {
    unsigned long long r;
    asm("mov.b64 %0, {%1, %2};" : "=l"(r) : "f"(x), "f"(y));
    return r;
}
__device__ __forceinline__ void fma2(unsigned long long& d,
                                     unsigned long long a, unsigned long long b) {
    asm("fma.rn.f32x2 %0, %1, %2, %0;" : "+l"(d) : "l"(a), "l"(b));
}
__device__ __forceinline__ float2 upk(unsigned long long v) {
    float2 r;
    asm("mov.b64 {%0, %1}, %2;" : "=f"(r.x), "=f"(r.y) : "l"(v));
    return r;
}

__device__ __forceinline__ float4 max4(float4 a, float4 b) {
    a.x = fmaxf(a.x, b.x); a.y = fmaxf(a.y, b.y);
    a.z = fmaxf(a.z, b.z); a.w = fmaxf(a.w, b.w);
    return a;
}

// ---------------- init: zero counts + dtype detection ------------------------
__global__ void init_kernel(const void* __restrict__ edge_raw) {
    int i = blockIdx.x * blockDim.x + threadIdx.x;
    if (i < N_NODES) g_counts[i] = 0;
    if (i == 0) {
        const long long* e64 = (const long long*)edge_raw;
        int ok64 = 1;
        #pragma unroll 8
        for (int t = 0; t < 64; t++) {
            long long v = e64[t];
            if (v < 0 || v >= N_NODES) ok64 = 0;
        }
        g_is64 = ok64;
    }
}

__device__ __forceinline__ int load_edge(const void* edge_raw, long long idx, int is64) {
    if (is64) return (int)((const long long*)edge_raw)[idx];
    return ((const int*)edge_raw)[idx];
}

// ---------------- CSR build -------------------------------------------------
__global__ void histogram_kernel(const void* __restrict__ edge_raw) {
    int e = blockIdx.x * blockDim.x + threadIdx.x;
    if (e >= N_EDGES) return;
    int dst = load_edge(edge_raw, (long long)N_EDGES + e, g_is64);
    if (dst < 0 || dst >= N_NODES) return;
    atomicAdd(&g_counts[dst], 1);
}

// phase 1: per-block exclusive scan + block totals
__global__ __launch_bounds__(SBLK) void scan1_kernel() {
    __shared__ int wsum[32];
    int tid = threadIdx.x, lane = tid & 31, w = tid >> 5;
    int i = blockIdx.x * SBLK + tid;
    int v = (i < N_NODES) ? g_counts[i] : 0;
    int x = v;
    #pragma unroll
    for (int off = 1; off < 32; off <<= 1) {
        int y = __shfl_up_sync(0xffffffffu, x, off);
        if (lane >= off) x += y;
    }
    if (lane == 31) wsum[w] = x;
    __syncthreads();
    if (w == 0) {
        int s = wsum[lane];
        #pragma unroll
        for (int off = 1; off < 32; off <<= 1) {
            int y = __shfl_up_sync(0xffffffffu, s, off);
            if (lane >= off) s += y;
        }
        wsum[lane] = s;
    }
    __syncthreads();
    int incl = x + ((w > 0) ? wsum[w - 1] : 0);
    if (i < N_NODES) g_rowptr[i] = incl - v;         // block-local exclusive
    if (tid == SBLK - 1) g_bsums[blockIdx.x] = incl; // block total
}

// phase 2: exclusive scan of NSB block totals (one 128-thread block)
__global__ void scan2_kernel() {
    __shared__ int wsum[4];
    int tid = threadIdx.x, lane = tid & 31, w = tid >> 5;
    int v = (tid < NSB) ? g_bsums[tid] : 0;
    int x = v;
    #pragma unroll
    for (int off = 1; off < 32; off <<= 1) {
        int y = __shfl_up_sync(0xffffffffu, x, off);
        if (lane >= off) x += y;
    }
    if (lane == 31) wsum[w] = x;
    __syncthreads();
    int wp = 0;
    for (int q = 0; q < w; q++) wp += wsum[q];
    int incl = x + wp;
    if (tid < NSB) g_bsums[tid] = incl - v;          // exclusive
    if (tid == 127) g_total = incl;                  // grand total (pads are 0)
}

// phase 3: add block offsets, init cursors, write rowptr[N]
__global__ __launch_bounds__(SBLK) void scan3_kernel() {
    int i = blockIdx.x * SBLK + threadIdx.x;
    if (i < N_NODES) {
        int r = g_rowptr[i] + g_bsums[blockIdx.x];
        g_rowptr[i] = r;
        g_cursor[i] = r;
    }
    if (blockIdx.x == 0 && threadIdx.x == 0) g_rowptr[N_NODES] = g_total;
}

__global__ void scatter_kernel(const void* __restrict__ edge_raw) {
    int e = blockIdx.x * blockDim.x + threadIdx.x;
    if (e >= N_EDGES) return;
    int is64 = g_is64;
    int src = load_edge(edge_raw, e, is64);
    int dst = load_edge(edge_raw, (long long)N_EDGES + e, is64);
    if (src < 0 || src >= N_NODES || dst < 0 || dst >= N_NODES) return;
    int pos = atomicAdd(&g_cursor[dst], 1);
    if (pos >= 0 && pos < N_EDGES) g_csr[pos] = src;
}

// ---------------- fused layer -----------------------------------------------
// Block = 128 nodes. Gather: warp split into 4 subgroups x 8 lanes; each
// subgroup owns one node, lane covers 8 floats (2x float4) of the row. 4 edges
// in flight per warp iteration, edge loop unrolled x2 (MLP ~ 4 rows).
// GEMM: warp (tile, half): lane = node, 32 output dims, packed f32x2 FMA.
__global__ __launch_bounds__(TPB) void layer_kernel(
    const float* __restrict__ x_ext, float* __restrict__ out_ext,
    const float* __restrict__ Wl, const float* __restrict__ bl,
    const float* __restrict__ Wr,
    int layer, int in_mode, int out_mode)
{
    extern __shared__ float smem[];
    float* sA = smem;
    float* sW = smem + SMEM_A_FLOATS;   // combined [128][64]: k<64 -> Wl, k>=64 -> Wr
    float* sB = sW + SMEM_W_FLOATS;

    const float* h_in  = (in_mode  == 0) ? x_ext  : ((in_mode  == 1) ? g_buf0 : g_buf1);
    float*       h_out = (out_mode == 0) ? out_ext : ((out_mode == 1) ? g_buf0 : g_buf1);

    int tid = threadIdx.x;
    {
        const float4* wl4 = (const float4*)(Wl + layer * D * D);
        const float4* wr4 = (const float4*)(Wr + layer * D * D);
        float4* sW4 = (float4*)sW;
        #pragma unroll
        for (int i = tid; i < D * D / 4; i += TPB) sW4[i] = wl4[i];
        #pragma unroll
        for (int i = tid; i < D * D / 4; i += TPB) sW4[D * D / 4 + i] = wr4[i];
        if (tid < D) sB[tid] = bl[layer * D + tid];
    }

    int warp = tid >> 5, lane = tid & 31;
    int tile = warp >> 1, half = warp & 1;
    int sub = lane >> 3;           // node subgroup 0..3
    int dl  = lane & 7;            // dim octet: floats [dl*8, dl*8+8)
    int blockBase = blockIdx.x * NPB;

    // ---- gather phase: 16 nodes per warp, 4-way parallel ----
    #pragma unroll 1
    for (int r = 0; r < 4; r++) {
        int nl = tile * 32 + half * 16 + r * 4 + sub;
        int node = blockBase + nl;
        bool valid = (node < N_NODES);
        int start = 0, end = 0;
        if (valid) { start = g_rowptr[node]; end = g_rowptr[node + 1]; }

        float4 m0 = make_float4(-INFINITY, -INFINITY, -INFINITY, -INFINITY);
        float4 m1 = m0;
        int j = start;
        #pragma unroll 1
        for (; j + 2 <= end; j += 2) {
            int s0 = g_csr[j];
            int s1 = g_csr[j + 1];
            const float4* p0 = (const float4*)(h_in + (size_t)s0 * D);
            const float4* p1 = (const float4*)(h_in + (size_t)s1 * D);
            float4 a0 = p0[dl * 2], a1 = p0[dl * 2 + 1];
            float4 b0 = p1[dl * 2], b1 = p1[dl * 2 + 1];
            m0 = max4(m0, a0); m1 = max4(m1, a1);
            m0 = max4(m0, b0); m1 = max4(m1, b1);
        }
        if (j < end) {
            int s0 = g_csr[j];
            const float4* p0 = (const float4*)(h_in + (size_t)s0 * D);
            m0 = max4(m0, p0[dl * 2]);
            m1 = max4(m1, p0[dl * 2 + 1]);
        }
        if (start == end) {         // empty segment -> 0 (PyG)
            m0 = make_float4(0.f, 0.f, 0.f, 0.f);
            m1 = m0;
        }

        float4 s0 = make_float4(0.f, 0.f, 0.f, 0.f), s1 = s0;
        if (valid) {
            const float4* ps = (const float4*)(h_in + (size_t)node * D);
            s0 = ps[dl * 2]; s1 = ps[dl * 2 + 1];
        }
        float* arow = sA + nl * PITCH;
        int o = dl * 8;
        arow[o + 0] = m0.x; arow[o + 1] = m0.y; arow[o + 2] = m0.z; arow[o + 3] = m0.w;
        arow[o + 4] = m1.x; arow[o + 5] = m1.y; arow[o + 6] = m1.z; arow[o + 7] = m1.w;
        arow[64 + o + 0] = s0.x; arow[64 + o + 1] = s0.y;
        arow[64 + o + 2] = s0.z; arow[64 + o + 3] = s0.w;
        arow[64 + o + 4] = s1.x; arow[64 + o + 5] = s1.y;
        arow[64 + o + 6] = s1.z; arow[64 + o + 7] = s1.w;
    }
    __syncthreads();

    // ---- GEMM phase: out = relu([agg|h] @ [Wl;Wr] + bl) ----
    int nl = tile * 32 + lane;           // lane = node within tile
    int node = blockBase + nl;
    const float* arow = sA + nl * PITCH;
    const float* wbase = sW + half * 32;

    unsigned long long acc[16];
    {
        const float* bb = sB + half * 32;
        #pragma unroll
        for (int j = 0; j < 16; j++) acc[j] = pk(bb[2 * j], bb[2 * j + 1]);
    }
    #pragma unroll 4
    for (int k = 0; k < 2 * D; k++) {
        float a = arow[k];                         // conflict-free (pitch 129)
        unsigned long long aa = pk(a, a);
        const ulonglong2* w2 = (const ulonglong2*)(wbase + k * D);
        #pragma unroll
        for (int j = 0; j < 8; j++) {
            ulonglong2 w = w2[j];                  // LDS.128 broadcast
            fma2(acc[2 * j],     aa, w.x);
            fma2(acc[2 * j + 1], aa, w.y);
        }
    }
    if (node < N_NODES) {
        float4* orow = (float4*)(h_out + node * D + half * 32);
        #pragma unroll
        for (int j = 0; j < 8; j++) {
            float2 p0 = upk(acc[2 * j]);
            float2 p1 = upk(acc[2 * j + 1]);
            float4 o;
            o.x = fmaxf(p0.x, 0.0f); o.y = fmaxf(p0.y, 0.0f);
            o.z = fmaxf(p1.x, 0.0f); o.w = fmaxf(p1.y, 0.0f);
            orow[j] = o;
        }
    }
}

// ---------------- launch -----------------------------------------------------
extern "C" void kernel_launch(void* const* d_in, const int* in_sizes, int n_in,
                              void* d_out, int out_size) {
    const float* x  = nullptr;
    const void*  edge = nullptr;
    const float* Wl = nullptr;
    const float* Wr = nullptr;
    const float* bl = nullptr;
    for (int i = 0; i < n_in; i++) {
        int sz = in_sizes[i];
        if (sz == N_NODES * D)            x    = (const float*)d_in[i];
        else if (sz == 2 * N_EDGES)       edge = d_in[i];
        else if (sz == N_LAYERS * D * D) { if (!Wl) Wl = (const float*)d_in[i];
                                           else     Wr = (const float*)d_in[i]; }
        else if (sz == N_LAYERS * D)      bl   = (const float*)d_in[i];
    }
    float* out = (float*)d_out;

    static int smem_set = 0;
    if (!smem_set) {
        cudaFuncSetAttribute(layer_kernel,
                             cudaFuncAttributeMaxDynamicSharedMemorySize, SMEM_BYTES);
        smem_set = 1;
    }

    init_kernel<<<(N_NODES + 255) / 256, 256>>>(edge);
    histogram_kernel<<<(N_EDGES + 255) / 256, 256>>>(edge);
    scan1_kernel<<<NSB, SBLK>>>();
    scan2_kernel<<<1, 128>>>();
    scan3_kernel<<<NSB, SBLK>>>();
    scatter_kernel<<<(N_EDGES + 255) / 256, 256>>>(edge);

    int blocks = (N_NODES + NPB - 1) / NPB;
    layer_kernel<<<blocks, TPB, SMEM_BYTES>>>(x, out, Wl, bl, Wr, 0, 0, 1);
    layer_kernel<<<blocks, TPB, SMEM_BYTES>>>(x, out, Wl, bl, Wr, 1, 1, 2);
    layer_kernel<<<blocks, TPB, SMEM_BYTES>>>(x, out, Wl, bl, Wr, 2, 2, 1);
    layer_kernel<<<blocks, TPB, SMEM_BYTES>>>(x, out, Wl, bl, Wr, 3, 1, 0);
}

// round 5
// speedup vs baseline: 1.5134x; 1.1234x over previous
#include <cuda_runtime.h>
#include <math.h>

#define N_NODES 100000
#define N_EDGES 1250000
#define D 64
#define N_LAYERS 4

// ---- gemm kernel config ----
#define TPB 256                       // 8 warps
#define N_TILES 4                     // 4 tiles of 32 nodes; 2 warps (dim-halves) per tile
#define NPB (N_TILES * 32)            // 128 nodes per block
#define PITCH 129                     // odd pitch -> conflict-free sA[lane][k] reads
#define SMEM_A_FLOATS (NPB * PITCH)
#define SMEM_W_FLOATS (2 * D * D)
#define SMEM_BYTES ((SMEM_A_FLOATS + SMEM_W_FLOATS + D) * 4)

// ---- gather kernel config ----
#define GTPB 256                      // 8 warps x 4 subgroups = 32 nodes per block
#define GNPB 32

// ---- scan config ----
#define SBLK 1024
#define NSB ((N_NODES + SBLK - 1) / SBLK)   // 98

// ---------------- scratch (static device globals) ---------------------------
__device__ float g_buf0[N_NODES * D];
__device__ float g_buf1[N_NODES * D];
__device__ float g_agg[N_NODES * D];
__device__ int   g_counts[N_NODES];
__device__ int   g_rowptr[N_NODES + 1];
__device__ int   g_cursor[N_NODES];
__device__ int   g_csr[N_EDGES];
__device__ int   g_bsums[NSB];
__device__ int   g_total;
__device__ int   g_is64;

// ---------------- packed f32x2 helpers --------------------------------------
__device__ __forceinline__ unsigned long long pk(float x, float y) {
    unsigned long long r;
    asm("mov.b64 %0, {%1, %2};" : "=l"(r) : "f"(x), "f"(y));
    return r;
}
__device__ __forceinline__ void fma2(unsigned long long& d,
                                     unsigned long long a, unsigned long long b) {
    asm("fma.rn.f32x2 %0, %1, %2, %0;" : "+l"(d) : "l"(a), "l"(b));
}
__device__ __forceinline__ float2 upk(unsigned long long v) {
    float2 r;
    asm("mov.b64 {%0, %1}, %2;" : "=f"(r.x), "=f"(r.y) : "l"(v));
    return r;
}
__device__ __forceinline__ float4 max4(float4 a, float4 b) {
    a.x = fmaxf(a.x, b.x); a.y = fmaxf(a.y, b.y);
    a.z = fmaxf(a.z, b.z); a.w = fmaxf(a.w, b.w);
    return a;
}

// ---------------- init: zero counts + dtype detection ------------------------
__global__ void init_kernel(const void* __restrict__ edge_raw) {
    int i = blockIdx.x * blockDim.x + threadIdx.x;
    if (i < N_NODES) g_counts[i] = 0;
    if (i == 0) {
        const long long* e64 = (const long long*)edge_raw;
        int ok64 = 1;
        #pragma unroll 8
        for (int t = 0; t < 64; t++) {
            long long v = e64[t];
            if (v < 0 || v >= N_NODES) ok64 = 0;
        }
        g_is64 = ok64;
    }
}

__device__ __forceinline__ int load_edge(const void* edge_raw, long long idx, int is64) {
    if (is64) return (int)((const long long*)edge_raw)[idx];
    return ((const int*)edge_raw)[idx];
}

// ---------------- CSR build -------------------------------------------------
__global__ void histogram_kernel(const void* __restrict__ edge_raw) {
    int e = blockIdx.x * blockDim.x + threadIdx.x;
    if (e >= N_EDGES) return;
    int dst = load_edge(edge_raw, (long long)N_EDGES + e, g_is64);
    if (dst < 0 || dst >= N_NODES) return;
    atomicAdd(&g_counts[dst], 1);
}

__global__ __launch_bounds__(SBLK) void scan1_kernel() {
    __shared__ int wsum[32];
    int tid = threadIdx.x, lane = tid & 31, w = tid >> 5;
    int i = blockIdx.x * SBLK + tid;
    int v = (i < N_NODES) ? g_counts[i] : 0;
    int x = v;
    #pragma unroll
    for (int off = 1; off < 32; off <<= 1) {
        int y = __shfl_up_sync(0xffffffffu, x, off);
        if (lane >= off) x += y;
    }
    if (lane == 31) wsum[w] = x;
    __syncthreads();
    if (w == 0) {
        int s = wsum[lane];
        #pragma unroll
        for (int off = 1; off < 32; off <<= 1) {
            int y = __shfl_up_sync(0xffffffffu, s, off);
            if (lane >= off) s += y;
        }
        wsum[lane] = s;
    }
    __syncthreads();
    int incl = x + ((w > 0) ? wsum[w - 1] : 0);
    if (i < N_NODES) g_rowptr[i] = incl - v;
    if (tid == SBLK - 1) g_bsums[blockIdx.x] = incl;
}

__global__ void scan2_kernel() {
    __shared__ int wsum[4];
    int tid = threadIdx.x, lane = tid & 31, w = tid >> 5;
    int v = (tid < NSB) ? g_bsums[tid] : 0;
    int x = v;
    #pragma unroll
    for (int off = 1; off < 32; off <<= 1) {
        int y = __shfl_up_sync(0xffffffffu, x, off);
        if (lane >= off) x += y;
    }
    if (lane == 31) wsum[w] = x;
    __syncthreads();
    int wp = 0;
    for (int q = 0; q < w; q++) wp += wsum[q];
    int incl = x + wp;
    if (tid < NSB) g_bsums[tid] = incl - v;
    if (tid == 127) g_total = incl;
}

__global__ __launch_bounds__(SBLK) void scan3_kernel() {
    int i = blockIdx.x * SBLK + threadIdx.x;
    if (i < N_NODES) {
        int r = g_rowptr[i] + g_bsums[blockIdx.x];
        g_rowptr[i] = r;
        g_cursor[i] = r;
    }
    if (blockIdx.x == 0 && threadIdx.x == 0) g_rowptr[N_NODES] = g_total;
}

__global__ void scatter_kernel(const void* __restrict__ edge_raw) {
    int e = blockIdx.x * blockDim.x + threadIdx.x;
    if (e >= N_EDGES) return;
    int is64 = g_is64;
    int src = load_edge(edge_raw, e, is64);
    int dst = load_edge(edge_raw, (long long)N_EDGES + e, is64);
    if (src < 0 || src >= N_NODES || dst < 0 || dst >= N_NODES) return;
    int pos = atomicAdd(&g_cursor[dst], 1);
    if (pos >= 0 && pos < N_EDGES) g_csr[pos] = src;
}

// ---------------- gather: segment max-pool -> g_agg -------------------------
// 8-lane subgroup per node (lane covers 8 floats = 2 float4), 4 nodes/warp,
// 32 nodes/block, no smem -> high occupancy for latency hiding.
__global__ __launch_bounds__(GTPB) void gather_kernel(
    const float* __restrict__ x_ext, int in_mode)
{
    const float* h_in = (in_mode == 0) ? x_ext : ((in_mode == 1) ? g_buf0 : g_buf1);
    int tid = threadIdx.x;
    int warp = tid >> 5, lane = tid & 31;
    int sub = lane >> 3, dl = lane & 7;

    int node = blockIdx.x * GNPB + warp * 4 + sub;
    if (node >= N_NODES) return;
    int start = g_rowptr[node];
    int end   = g_rowptr[node + 1];

    float4 m0 = make_float4(-INFINITY, -INFINITY, -INFINITY, -INFINITY);
    float4 m1 = m0;
    int j = start;
    #pragma unroll 1
    for (; j + 2 <= end; j += 2) {
        int s0 = g_csr[j];
        int s1 = g_csr[j + 1];
        const float4* p0 = (const float4*)(h_in + (size_t)s0 * D);
        const float4* p1 = (const float4*)(h_in + (size_t)s1 * D);
        float4 a0 = p0[dl * 2], a1 = p0[dl * 2 + 1];
        float4 b0 = p1[dl * 2], b1 = p1[dl * 2 + 1];
        m0 = max4(m0, a0); m1 = max4(m1, a1);
        m0 = max4(m0, b0); m1 = max4(m1, b1);
    }
    if (j < end) {
        int s0 = g_csr[j];
        const float4* p0 = (const float4*)(h_in + (size_t)s0 * D);
        m0 = max4(m0, p0[dl * 2]);
        m1 = max4(m1, p0[dl * 2 + 1]);
    }
    if (start == end) {               // empty segment -> 0 (PyG)
        m0 = make_float4(0.f, 0.f, 0.f, 0.f);
        m1 = m0;
    }
    float4* arow = (float4*)(g_agg + (size_t)node * D);
    arow[dl * 2]     = m0;
    arow[dl * 2 + 1] = m1;
}

// ---------------- gemm: out = relu([agg|h] @ [Wl;Wr] + bl) -------------------
__global__ __launch_bounds__(TPB) void gemm_kernel(
    const float* __restrict__ x_ext, float* __restrict__ out_ext,
    const float* __restrict__ Wl, const float* __restrict__ bl,
    const float* __restrict__ Wr,
    int layer, int in_mode, int out_mode)
{
    extern __shared__ float smem[];
    float* sA = smem;                    // [128][129]: cols 0..63 agg, 64..127 self
    float* sW = smem + SMEM_A_FLOATS;    // [128][64]:  k<64 -> Wl, k>=64 -> Wr
    float* sB = sW + SMEM_W_FLOATS;

    const float* h_in  = (in_mode  == 0) ? x_ext  : ((in_mode  == 1) ? g_buf0 : g_buf1);
    float*       h_out = (out_mode == 0) ? out_ext : ((out_mode == 1) ? g_buf0 : g_buf1);

    int tid = threadIdx.x;
    int blockBase = blockIdx.x * NPB;
    {
        const float4* wl4 = (const float4*)(Wl + layer * D * D);
        const float4* wr4 = (const float4*)(Wr + layer * D * D);
        float4* sW4 = (float4*)sW;
        #pragma unroll
        for (int i = tid; i < D * D / 4; i += TPB) sW4[i] = wl4[i];
        #pragma unroll
        for (int i = tid; i < D * D / 4; i += TPB) sW4[D * D / 4 + i] = wr4[i];
        if (tid < D) sB[tid] = bl[layer * D + tid];
    }
    // stage A = [agg | h] (coalesced float4 global loads, scalar pitched stores)
    #pragma unroll 2
    for (int i = tid; i < NPB * (D / 4); i += TPB) {
        int row = i >> 4, c4 = i & 15;
        int node = blockBase + row;
        float4 va = make_float4(0.f, 0.f, 0.f, 0.f), vh = va;
        if (node < N_NODES) {
            va = ((const float4*)(g_agg + (size_t)node * D))[c4];
            vh = ((const float4*)(h_in  + (size_t)node * D))[c4];
        }
        float* arow = sA + row * PITCH;
        int o = c4 * 4;
        arow[o] = va.x; arow[o + 1] = va.y; arow[o + 2] = va.z; arow[o + 3] = va.w;
        arow[64 + o] = vh.x; arow[64 + o + 1] = vh.y;
        arow[64 + o + 2] = vh.z; arow[64 + o + 3] = vh.w;
    }
    __syncthreads();

    int warp = tid >> 5, lane = tid & 31;
    int tile = warp >> 1, half = warp & 1;
    int nl = tile * 32 + lane;
    int node = blockBase + nl;
    const float* arow = sA + nl * PITCH;
    const float* wbase = sW + half * 32;

    unsigned long long acc[16];
    {
        const float* bb = sB + half * 32;
        #pragma unroll
        for (int j = 0; j < 16; j++) acc[j] = pk(bb[2 * j], bb[2 * j + 1]);
    }
    #pragma unroll 4
    for (int k = 0; k < 2 * D; k++) {
        float a = arow[k];                         // conflict-free (pitch 129)
        unsigned long long aa = pk(a, a);
        const ulonglong2* w2 = (const ulonglong2*)(wbase + k * D);
        #pragma unroll
        for (int j = 0; j < 8; j++) {
            ulonglong2 w = w2[j];                  // LDS.128 broadcast
            fma2(acc[2 * j],     aa, w.x);
            fma2(acc[2 * j + 1], aa, w.y);
        }
    }
    if (node < N_NODES) {
        float4* orow = (float4*)(h_out + node * D + half * 32);
        #pragma unroll
        for (int j = 0; j < 8; j++) {
            float2 p0 = upk(acc[2 * j]);
            float2 p1 = upk(acc[2 * j + 1]);
            float4 o;
            o.x = fmaxf(p0.x, 0.0f); o.y = fmaxf(p0.y, 0.0f);
            o.z = fmaxf(p1.x, 0.0f); o.w = fmaxf(p1.y, 0.0f);
            orow[j] = o;
        }
    }
}

// ---------------- launch -----------------------------------------------------
extern "C" void kernel_launch(void* const* d_in, const int* in_sizes, int n_in,
                              void* d_out, int out_size) {
    const float* x  = nullptr;
    const void*  edge = nullptr;
    const float* Wl = nullptr;
    const float* Wr = nullptr;
    const float* bl = nullptr;
    for (int i = 0; i < n_in; i++) {
        int sz = in_sizes[i];
        if (sz == N_NODES * D)            x    = (const float*)d_in[i];
        else if (sz == 2 * N_EDGES)       edge = d_in[i];
        else if (sz == N_LAYERS * D * D) { if (!Wl) Wl = (const float*)d_in[i];
                                           else     Wr = (const float*)d_in[i]; }
        else if (sz == N_LAYERS * D)      bl   = (const float*)d_in[i];
    }
    float* out = (float*)d_out;

    static int smem_set = 0;
    if (!smem_set) {
        cudaFuncSetAttribute(gemm_kernel,
                             cudaFuncAttributeMaxDynamicSharedMemorySize, SMEM_BYTES);
        smem_set = 1;
    }

    init_kernel<<<(N_NODES + 255) / 256, 256>>>(edge);
    histogram_kernel<<<(N_EDGES + 255) / 256, 256>>>(edge);
    scan1_kernel<<<NSB, SBLK>>>();
    scan2_kernel<<<1, 128>>>();
    scan3_kernel<<<NSB, SBLK>>>();
    scatter_kernel<<<(N_EDGES + 255) / 256, 256>>>(edge);

    int gblocks = (N_NODES + GNPB - 1) / GNPB;
    int mblocks = (N_NODES + NPB - 1) / NPB;
    // ping-pong: x -> buf0 -> buf1 -> buf0 -> out
    const int im[4] = {0, 1, 2, 1};
    const int om[4] = {1, 2, 1, 0};
    for (int l = 0; l < N_LAYERS; l++) {
        gather_kernel<<<gblocks, GTPB>>>(x, im[l]);
        gemm_kernel<<<mblocks, TPB, SMEM_BYTES>>>(x, out, Wl, bl, Wr, l, im[l], om[l]);
    }
}